// round 15
// baseline (speedup 1.0000x reference)
#include <cuda_runtime.h>
#include <cuda_bf16.h>
#include <cstdint>

// Problem dims (fixed by the dataset): N=100000, E=1000000, in=out=64
#define MAXN 100000
#define MAXE 1000000
#define DIM 64
#define BUCKET 64          // per-node edge bucket capacity (deg ~ Poisson(10))

// ---------------- scratch (static device globals; no allocation) -----------
__device__ float g_h0[MAXN * DIM];   // h for branch 0 (login)
__device__ float g_h1[MAXN * DIM];   // h for branch 1 (exec)
__device__ float g_s0[MAXN], g_d0[MAXN], g_s1[MAXN], g_d1[MAXN];

__device__ int    g_cnt[MAXN];              // per-dst in-degree / insert cursor
__device__ float2 g_bucket[MAXN * BUCKET];  // {bits(src|type<<30), p}, 51.2 MB

__device__ __forceinline__ float leakyf(float v) {
    return v > 0.f ? v : 0.2f * v;
}

// Packed f32x2 FMA (Blackwell-only; 2x fp32 FMA throughput)
#define FMA_F32X2(d, a, b, c) \
    asm("fma.rn.f32x2 %0, %1, %2, %3;" \
        : "=l"(d) : "l"(a), "l"(b), "l"(c))
#define PACK2(out, lo, hi) \
    asm("mov.b64 %0, {%1, %2};" : "=l"(out) : "r"(lo), "r"(hi))
#define UNPACK2(lo, hi, in) \
    asm("mov.b64 {%0, %1}, %2;" : "=r"(lo), "=r"(hi) : "l"(in))

#define XS_STRIDE 10   // floats per k-row (8 nodes + 2 pad; even for LDS.64 align)

// ---------------- K0: s/d scalars via projected vectors; cnt=0 --------------
// wa = [W0@as0, W0@ad0, W1@as1, W1@ad1] computed per block in smem (64 FMA
// per thread), then half-warp per node with grid-stride. 296 blocks keep the
// redundant W reads to ~9.5 MB.
__global__ __launch_bounds__(256) void k_sd(
    const float* __restrict__ x,
    const float* __restrict__ W0, const float* __restrict__ W1,
    const float* __restrict__ as0, const float* __restrict__ ad0,
    const float* __restrict__ as1, const float* __restrict__ ad1,
    int N)
{
    __shared__ float wa[4 * DIM];
    int tid = threadIdx.x;
    {
        int v = tid >> 6, k = tid & 63;
        const float* W = (v < 2) ? W0 : W1;
        const float* a = (v == 0) ? as0 : (v == 1) ? ad0 : (v == 2) ? as1 : ad1;
        float s = 0.f;
#pragma unroll 16
        for (int c = 0; c < DIM; c++) s = fmaf(W[k * DIM + c], a[c], s);
        wa[tid] = s;
    }
    __syncthreads();

    int lane = tid & 31;
    int sub = lane >> 4;
    int l = lane & 15;
    int warpInBlock = tid >> 5;

    const float* w0 = wa + 4 * l;
    const float* w1 = wa + DIM + 4 * l;
    const float* w2 = wa + 2 * DIM + 4 * l;
    const float* w3 = wa + 3 * DIM + 4 * l;

    // grid-stride over nodes, 16 nodes per block-iteration
    int nodesPerBlock = 16;
    for (int base = blockIdx.x * nodesPerBlock; base < N;
         base += gridDim.x * nodesPerBlock) {
        int node = base + warpInBlock * 2 + sub;
        if (node >= N) continue;

        float4 xv = *reinterpret_cast<const float4*>(x + (size_t)node * DIM + 4 * l);
        float p0 = xv.x * w0[0] + xv.y * w0[1] + xv.z * w0[2] + xv.w * w0[3];
        float p1 = xv.x * w1[0] + xv.y * w1[1] + xv.z * w1[2] + xv.w * w1[3];
        float p2 = xv.x * w2[0] + xv.y * w2[1] + xv.z * w2[2] + xv.w * w2[3];
        float p3 = xv.x * w3[0] + xv.y * w3[1] + xv.z * w3[2] + xv.w * w3[3];
#pragma unroll
        for (int off = 8; off > 0; off >>= 1) {
            p0 += __shfl_down_sync(0xffffffffu, p0, off, 16);
            p1 += __shfl_down_sync(0xffffffffu, p1, off, 16);
            p2 += __shfl_down_sync(0xffffffffu, p2, off, 16);
            p3 += __shfl_down_sync(0xffffffffu, p3, off, 16);
        }
        if (l == 0) {
            g_s0[node] = p0;
            g_d0[node] = p1;
            g_s1[node] = p2;
            g_d1[node] = p3;
            g_cnt[node] = 0;
        }
    }
}

// ---------------- K1: h = x@W via fma.rn.f32x2 (slim, 64 regs, 4 blk/SM) ----
__global__ __launch_bounds__(256) void k_gemm(
    const float* __restrict__ x,
    const float* __restrict__ W0, const float* __restrict__ W1,
    int N)
{
    __shared__ float Ws[2 * DIM * DIM];          // [mat][k][col], 32 KB
    __shared__ float xs[8][DIM * XS_STRIDE];     // k-major per warp, 20 KB

    int tid = threadIdx.x;
    for (int i = tid; i < DIM * DIM; i += 256) {
        Ws[i] = W0[i];
        Ws[DIM * DIM + i] = W1[i];
    }
    __syncthreads();

    int warp = tid >> 5, lane = tid & 31;
    int sel = lane >> 4;          // 0 -> branch0, 1 -> branch1
    int li  = lane & 15;          // 16 lanes cover 64 cols (4 each)
    const float* myW = Ws + sel * DIM * DIM;
    float* myH = sel ? g_h1 : g_h0;

    int nChunks = (N + 7) >> 3;
    for (int chunk = blockIdx.x * 8 + warp; chunk < nChunks; chunk += gridDim.x * 8) {
        int base = chunk * 8;
        int count = min(8, N - base);

        // stage x transposed: xs[k*XS_STRIDE + r] = x[base+r][k]
        {
            const float4* x4 = reinterpret_cast<const float4*>(x) + (size_t)base * 16;
            float* xw = xs[warp];
            for (int i = lane; i < 128; i += 32) {
                int r = i >> 4, k4 = i & 15;
                float4 v = (r < count) ? x4[i] : make_float4(0.f, 0.f, 0.f, 0.f);
                xw[(4 * k4 + 0) * XS_STRIDE + r] = v.x;
                xw[(4 * k4 + 1) * XS_STRIDE + r] = v.y;
                xw[(4 * k4 + 2) * XS_STRIDE + r] = v.z;
                xw[(4 * k4 + 3) * XS_STRIDE + r] = v.w;
            }
        }
        __syncwarp();

        unsigned long long accp[4][4];
#pragma unroll
        for (int p = 0; p < 4; p++)
#pragma unroll
            for (int c = 0; c < 4; c++) accp[p][c] = 0ull;

        const float* xw = xs[warp];
#pragma unroll 8
        for (int k = 0; k < DIM; k++) {
            float4 wv = *reinterpret_cast<const float4*>(myW + k * DIM + 4 * li);
            unsigned long long b[4];
            PACK2(b[0], __float_as_uint(wv.x), __float_as_uint(wv.x));
            PACK2(b[1], __float_as_uint(wv.y), __float_as_uint(wv.y));
            PACK2(b[2], __float_as_uint(wv.z), __float_as_uint(wv.z));
            PACK2(b[3], __float_as_uint(wv.w), __float_as_uint(wv.w));
            const float* xrow = xw + k * XS_STRIDE;
#pragma unroll
            for (int p = 0; p < 4; p++) {
                unsigned long long a =
                    *reinterpret_cast<const unsigned long long*>(xrow + 2 * p);
                FMA_F32X2(accp[p][0], a, b[0], accp[p][0]);
                FMA_F32X2(accp[p][1], a, b[1], accp[p][1]);
                FMA_F32X2(accp[p][2], a, b[2], accp[p][2]);
                FMA_F32X2(accp[p][3], a, b[3], accp[p][3]);
            }
        }

        // slim epilogue: unpack pair-by-pair, store h rows
#pragma unroll
        for (int p = 0; p < 4; p++) {
            unsigned lo0, hi0, lo1, hi1, lo2, hi2, lo3, hi3;
            UNPACK2(lo0, hi0, accp[p][0]);
            UNPACK2(lo1, hi1, accp[p][1]);
            UNPACK2(lo2, hi2, accp[p][2]);
            UNPACK2(lo3, hi3, accp[p][3]);
            int r0 = 2 * p, r1 = 2 * p + 1;
            if (r0 < count) {
                float4 hv = make_float4(__uint_as_float(lo0), __uint_as_float(lo1),
                                        __uint_as_float(lo2), __uint_as_float(lo3));
                *reinterpret_cast<float4*>(myH + (size_t)(base + r0) * DIM + 4 * li) = hv;
            }
            if (r1 < count) {
                float4 hv = make_float4(__uint_as_float(hi0), __uint_as_float(hi1),
                                        __uint_as_float(hi2), __uint_as_float(hi3));
                *reinterpret_cast<float4*>(myH + (size_t)(base + r1) * DIM + 4 * li) = hv;
            }
        }
        __syncwarp();
    }
}

// ---------------- K2: edge pass — p + bucket placement -----------------------
__global__ __launch_bounds__(256) void k_place(
    const int* __restrict__ src, const int* __restrict__ dst,
    const int* __restrict__ etype, int E)
{
    int e4 = blockIdx.x * 256 + threadIdx.x;
    int base = e4 * 4;
    if (base >= E) return;

    int nE = min(4, E - base);
    int ss[4], dd[4], tt[4];
    if (nE == 4) {
        int4 sv = reinterpret_cast<const int4*>(src)[e4];
        int4 dv = reinterpret_cast<const int4*>(dst)[e4];
        int4 tv = reinterpret_cast<const int4*>(etype)[e4];
        ss[0] = sv.x; ss[1] = sv.y; ss[2] = sv.z; ss[3] = sv.w;
        dd[0] = dv.x; dd[1] = dv.y; dd[2] = dv.z; dd[3] = dv.w;
        tt[0] = tv.x; tt[1] = tv.y; tt[2] = tv.z; tt[3] = tv.w;
    } else {
        for (int i = 0; i < nE; i++) {
            ss[i] = src[base + i]; dd[i] = dst[base + i]; tt[i] = etype[base + i];
        }
    }
#pragma unroll 4
    for (int i = 0; i < 4; i++) {
        if (i >= nE) break;
        int s = ss[i], d = dd[i], t = tt[i];
        float sv = t ? g_s1[s] : g_s0[s];
        float dv = t ? g_d1[d] : g_d0[d];
        float p = __expf(leakyf(sv + dv));
        int pos = atomicAdd(&g_cnt[d], 1);
        if (pos < BUCKET)   // unreachable for Poisson(10) degrees; guards OOB
            g_bucket[(size_t)d * BUCKET + pos] =
                make_float2(__int_as_float(s | (t << 30)), p);
    }
}

// ---------------- K3: gather — out[d] = Σ_t (acc_t + self_t·h_t)/den_t + b --
__global__ __launch_bounds__(256) void k_gather(
    const float* __restrict__ b0, const float* __restrict__ b1,
    float* __restrict__ out, int N)
{
    int gw = (blockIdx.x * blockDim.x + threadIdx.x) >> 5;
    int lane = threadIdx.x & 31;
    int sub = lane >> 4;
    int l = lane & 15;

    float4 bv;
    {
        float4 bb0 = reinterpret_cast<const float4*>(b0)[l];
        float4 bb1 = reinterpret_cast<const float4*>(b1)[l];
        bv = make_float4(bb0.x + bb1.x, bb0.y + bb1.y, bb0.z + bb1.z, bb0.w + bb1.w);
    }

    int node = gw * 2 + sub;
    bool live = node < N;
    int nc = live ? node : (N - 1);

    float selfp0 = __expf(leakyf(g_s0[nc] + g_d0[nc]));
    float selfp1 = __expf(leakyf(g_s1[nc] + g_d1[nc]));
    float den0 = selfp0, den1 = selfp1;

    const float4* h0r = reinterpret_cast<const float4*>(g_h0);
    const float4* h1r = reinterpret_cast<const float4*>(g_h1);

    float4 acc0 = make_float4(0.f, 0.f, 0.f, 0.f);
    float4 acc1 = make_float4(0.f, 0.f, 0.f, 0.f);

    int cnt = min(g_cnt[nc], BUCKET);
    const float2* bucket = g_bucket + (size_t)nc * BUCKET;
    for (int ei = 0; ei < cnt; ei++) {
        float2 ev = bucket[ei];                 // uniform address -> broadcast
        int pk = __float_as_int(ev.x);
        int s = pk & 0x3FFFFFFF;
        float ft = (float)(((unsigned)pk) >> 30);
        float w1 = ev.y * ft;
        float w0 = ev.y - w1;
        den0 += w0; den1 += w1;
        const float4* hp = (ft != 0.f ? h1r : h0r) + (size_t)s * 16;
        float4 hv = hp[l];
        acc0.x = fmaf(w0, hv.x, acc0.x); acc1.x = fmaf(w1, hv.x, acc1.x);
        acc0.y = fmaf(w0, hv.y, acc0.y); acc1.y = fmaf(w1, hv.y, acc1.y);
        acc0.z = fmaf(w0, hv.z, acc0.z); acc1.z = fmaf(w1, hv.z, acc1.z);
        acc0.w = fmaf(w0, hv.w, acc0.w); acc1.w = fmaf(w1, hv.w, acc1.w);
    }

    float4 hv0 = h0r[(size_t)nc * 16 + l];
    float4 hv1 = h1r[(size_t)nc * 16 + l];
    float rd0 = 1.f / den0, rd1 = 1.f / den1;
    float4 o;
    o.x = (acc0.x + selfp0 * hv0.x) * rd0 + (acc1.x + selfp1 * hv1.x) * rd1 + bv.x;
    o.y = (acc0.y + selfp0 * hv0.y) * rd0 + (acc1.y + selfp1 * hv1.y) * rd1 + bv.y;
    o.z = (acc0.z + selfp0 * hv0.z) * rd0 + (acc1.z + selfp1 * hv1.z) * rd1 + bv.z;
    o.w = (acc0.w + selfp0 * hv0.w) * rd0 + (acc1.w + selfp1 * hv1.w) * rd1 + bv.w;

    if (live)
        reinterpret_cast<float4*>(out)[(size_t)node * 16 + l] = o;
}

// ---------------- launch -----------------------------------------------------
extern "C" void kernel_launch(void* const* d_in, const int* in_sizes, int n_in,
                              void* d_out, int out_size)
{
    const float* x   = (const float*)d_in[0];
    const int*   ei  = (const int*)  d_in[1];
    const int*   et  = (const int*)  d_in[2];
    const float* W0  = (const float*)d_in[3];
    const float* as0 = (const float*)d_in[4];
    const float* ad0 = (const float*)d_in[5];
    const float* b0  = (const float*)d_in[6];
    const float* W1  = (const float*)d_in[7];
    const float* as1 = (const float*)d_in[8];
    const float* ad1 = (const float*)d_in[9];
    const float* b1  = (const float*)d_in[10];
    float* out = (float*)d_out;

    int N = in_sizes[0] / DIM;
    int E = in_sizes[1] / 2;
    if (N > MAXN) N = MAXN;
    if (E > MAXE) E = MAXE;

    const int* srcp = ei;
    const int* dstp = ei + E;

    // Slim gemm: 64 regs -> 4 blocks/SM. One resident wave = 148 x 4 = 592.
    int nChunks = (N + 7) / 8;
    int gemmBlocks = (nChunks + 7) / 8;
    if (gemmBlocks > 592) gemmBlocks = 592;

    k_sd    <<<296, 256>>>(x, W0, W1, as0, ad0, as1, ad1, N);
    k_gemm  <<<gemmBlocks, 256>>>(x, W0, W1, N);
    k_place <<<(E / 4 + 255) / 256 + 1, 256>>>(srcp, dstp, et, E);
    k_gather<<<(N + 15) / 16, 256>>>(b0, b1, out, N);
}

// round 16
// speedup vs baseline: 1.0834x; 1.0834x over previous
#include <cuda_runtime.h>
#include <cuda_bf16.h>
#include <cstdint>

// Problem dims (fixed by the dataset): N=100000, E=1000000, in=out=64
#define MAXN 100000
#define MAXE 1000000
#define DIM 64
#define BUCKET 64          // per-node edge bucket capacity (deg ~ Poisson(10))

// ---------------- scratch (static device globals; no allocation) -----------
__device__ float g_h0[MAXN * DIM];   // h for branch 0 (login)
__device__ float g_h1[MAXN * DIM];   // h for branch 1 (exec)
__device__ float g_s0[MAXN], g_d0[MAXN], g_s1[MAXN], g_d1[MAXN];

__device__ int g_cnt[MAXN];               // per-dst in-degree / insert cursor
__device__ int g_bucket[MAXN * BUCKET];   // src | (type<<30), 25.6 MB

__device__ __forceinline__ float leakyf(float v) {
    return v > 0.f ? v : 0.2f * v;
}

// Packed f32x2 FMA (Blackwell-only; 2x fp32 FMA throughput)
#define FMA_F32X2(d, a, b, c) \
    asm("fma.rn.f32x2 %0, %1, %2, %3;" \
        : "=l"(d) : "l"(a), "l"(b), "l"(c))
#define PACK2(out, lo, hi) \
    asm("mov.b64 %0, {%1, %2};" : "=l"(out) : "r"(lo), "r"(hi))
#define UNPACK2(lo, hi, in) \
    asm("mov.b64 {%0, %1}, %2;" : "=r"(lo), "=r"(hi) : "l"(in))

#define XS_STRIDE 10   // floats per k-row (8 nodes + 2 pad; even for LDS.64 align)

// ---------------- K1: h = x@W via fma.rn.f32x2; s/d scalars; cnt=0 ----------
// (R13 structure: s/d from in-register h — no extra x pass.)
__global__ __launch_bounds__(256) void k_gemm(
    const float* __restrict__ x,
    const float* __restrict__ W0, const float* __restrict__ W1,
    const float* __restrict__ as0, const float* __restrict__ ad0,
    const float* __restrict__ as1, const float* __restrict__ ad1,
    int N)
{
    __shared__ float Ws[2 * DIM * DIM];          // [mat][k][col], 32 KB
    __shared__ float xs[8][DIM * XS_STRIDE];     // k-major per warp, 20 KB

    int tid = threadIdx.x;
    for (int i = tid; i < DIM * DIM; i += 256) {
        Ws[i] = W0[i];
        Ws[DIM * DIM + i] = W1[i];
    }
    __syncthreads();

    int warp = tid >> 5, lane = tid & 31;
    int sel = lane >> 4;          // 0 -> branch0, 1 -> branch1
    int li  = lane & 15;          // 16 lanes cover 64 cols (4 each)
    const float* myW = Ws + sel * DIM * DIM;
    float4 asv = *reinterpret_cast<const float4*>((sel ? as1 : as0) + 4 * li);
    float4 adv = *reinterpret_cast<const float4*>((sel ? ad1 : ad0) + 4 * li);
    float* myH = sel ? g_h1 : g_h0;
    float* myS = sel ? g_s1 : g_s0;
    float* myD = sel ? g_d1 : g_d0;

    int nChunks = (N + 7) >> 3;
    for (int chunk = blockIdx.x * 8 + warp; chunk < nChunks; chunk += gridDim.x * 8) {
        int base = chunk * 8;
        int count = min(8, N - base);

        // stage x transposed: xs[k*XS_STRIDE + r] = x[base+r][k]
        {
            const float4* x4 = reinterpret_cast<const float4*>(x) + (size_t)base * 16;
            float* xw = xs[warp];
            for (int i = lane; i < 128; i += 32) {
                int r = i >> 4, k4 = i & 15;
                float4 v = (r < count) ? x4[i] : make_float4(0.f, 0.f, 0.f, 0.f);
                xw[(4 * k4 + 0) * XS_STRIDE + r] = v.x;
                xw[(4 * k4 + 1) * XS_STRIDE + r] = v.y;
                xw[(4 * k4 + 2) * XS_STRIDE + r] = v.z;
                xw[(4 * k4 + 3) * XS_STRIDE + r] = v.w;
            }
        }
        __syncwarp();

        unsigned long long accp[4][4];
#pragma unroll
        for (int p = 0; p < 4; p++)
#pragma unroll
            for (int c = 0; c < 4; c++) accp[p][c] = 0ull;

        const float* xw = xs[warp];
#pragma unroll 8
        for (int k = 0; k < DIM; k++) {
            float4 wv = *reinterpret_cast<const float4*>(myW + k * DIM + 4 * li);
            unsigned long long b[4];
            PACK2(b[0], __float_as_uint(wv.x), __float_as_uint(wv.x));
            PACK2(b[1], __float_as_uint(wv.y), __float_as_uint(wv.y));
            PACK2(b[2], __float_as_uint(wv.z), __float_as_uint(wv.z));
            PACK2(b[3], __float_as_uint(wv.w), __float_as_uint(wv.w));
            const float* xrow = xw + k * XS_STRIDE;
#pragma unroll
            for (int p = 0; p < 4; p++) {
                unsigned long long a =
                    *reinterpret_cast<const unsigned long long*>(xrow + 2 * p);
                FMA_F32X2(accp[p][0], a, b[0], accp[p][0]);
                FMA_F32X2(accp[p][1], a, b[1], accp[p][1]);
                FMA_F32X2(accp[p][2], a, b[2], accp[p][2]);
                FMA_F32X2(accp[p][3], a, b[3], accp[p][3]);
            }
        }

        float hval[8][4];
#pragma unroll
        for (int p = 0; p < 4; p++)
#pragma unroll
            for (int c = 0; c < 4; c++) {
                unsigned lo, hi;
                UNPACK2(lo, hi, accp[p][c]);
                hval[2 * p][c] = __uint_as_float(lo);
                hval[2 * p + 1][c] = __uint_as_float(hi);
            }

        for (int r = 0; r < count; r++) {
            int node = base + r;
            float4 hv = make_float4(hval[r][0], hval[r][1], hval[r][2], hval[r][3]);
            *reinterpret_cast<float4*>(myH + (size_t)node * DIM + 4 * li) = hv;

            float ps = hv.x * asv.x + hv.y * asv.y + hv.z * asv.z + hv.w * asv.w;
            float pd = hv.x * adv.x + hv.y * adv.y + hv.z * adv.z + hv.w * adv.w;
#pragma unroll
            for (int off = 8; off > 0; off >>= 1) {
                ps += __shfl_down_sync(0xffffffffu, ps, off, 16);
                pd += __shfl_down_sync(0xffffffffu, pd, off, 16);
            }
            if (li == 0) {
                myS[node] = ps;
                myD[node] = pd;
                if (sel == 0) g_cnt[node] = 0;   // bucket cursor reset
            }
        }
        __syncwarp();
    }
}

// ---------------- K2: edge pass — bucket placement only ----------------------
// No s/d loads, no expf: just pack src|type into the destination's bucket.
__global__ __launch_bounds__(256) void k_place(
    const int* __restrict__ src, const int* __restrict__ dst,
    const int* __restrict__ etype, int E)
{
    int e4 = blockIdx.x * 256 + threadIdx.x;
    int base = e4 * 4;
    if (base >= E) return;

    int nE = min(4, E - base);
    int ss[4], dd[4], tt[4];
    if (nE == 4) {
        int4 sv = reinterpret_cast<const int4*>(src)[e4];
        int4 dv = reinterpret_cast<const int4*>(dst)[e4];
        int4 tv = reinterpret_cast<const int4*>(etype)[e4];
        ss[0] = sv.x; ss[1] = sv.y; ss[2] = sv.z; ss[3] = sv.w;
        dd[0] = dv.x; dd[1] = dv.y; dd[2] = dv.z; dd[3] = dv.w;
        tt[0] = tv.x; tt[1] = tv.y; tt[2] = tv.z; tt[3] = tv.w;
    } else {
        for (int i = 0; i < nE; i++) {
            ss[i] = src[base + i]; dd[i] = dst[base + i]; tt[i] = etype[base + i];
        }
    }
#pragma unroll 4
    for (int i = 0; i < 4; i++) {
        if (i >= nE) break;
        int d = dd[i];
        int pos = atomicAdd(&g_cnt[d], 1);
        if (pos < BUCKET)   // unreachable for Poisson(10) degrees; guards OOB
            g_bucket[(size_t)d * BUCKET + pos] = ss[i] | (tt[i] << 30);
    }
}

// ---------------- K3: gather — p computed in-flight; softmax + h mix ---------
__global__ __launch_bounds__(256) void k_gather(
    const float* __restrict__ b0, const float* __restrict__ b1,
    float* __restrict__ out, int N)
{
    int gw = (blockIdx.x * blockDim.x + threadIdx.x) >> 5;
    int lane = threadIdx.x & 31;
    int sub = lane >> 4;
    int l = lane & 15;

    float4 bv;
    {
        float4 bb0 = reinterpret_cast<const float4*>(b0)[l];
        float4 bb1 = reinterpret_cast<const float4*>(b1)[l];
        bv = make_float4(bb0.x + bb1.x, bb0.y + bb1.y, bb0.z + bb1.z, bb0.w + bb1.w);
    }

    int node = gw * 2 + sub;
    bool live = node < N;
    int nc = live ? node : (N - 1);

    float sd0 = g_s0[nc], dd0 = g_d0[nc];
    float sd1 = g_s1[nc], dd1 = g_d1[nc];
    float selfp0 = __expf(leakyf(sd0 + dd0));
    float selfp1 = __expf(leakyf(sd1 + dd1));
    float den0 = selfp0, den1 = selfp1;

    const float4* h0r = reinterpret_cast<const float4*>(g_h0);
    const float4* h1r = reinterpret_cast<const float4*>(g_h1);

    float4 acc0 = make_float4(0.f, 0.f, 0.f, 0.f);
    float4 acc1 = make_float4(0.f, 0.f, 0.f, 0.f);

    int cnt = min(g_cnt[nc], BUCKET);
    const int* bucket = g_bucket + (size_t)nc * BUCKET;
    for (int ei = 0; ei < cnt; ei++) {
        int pk = bucket[ei];                    // uniform address -> broadcast
        int s = pk & 0x3FFFFFFF;
        int t = ((unsigned)pk) >> 30;
        // p = exp(leaky(s_t[src] + d_t[dst])) computed in-flight
        float sv = t ? g_s1[s] : g_s0[s];       // uniform broadcast load
        float p = __expf(leakyf(sv + (t ? dd1 : dd0)));
        float ft = (float)t;
        float w1 = p * ft;
        float w0 = p - w1;
        den0 += w0; den1 += w1;
        const float4* hp = (t ? h1r : h0r) + (size_t)s * 16;
        float4 hv = hp[l];
        acc0.x = fmaf(w0, hv.x, acc0.x); acc1.x = fmaf(w1, hv.x, acc1.x);
        acc0.y = fmaf(w0, hv.y, acc0.y); acc1.y = fmaf(w1, hv.y, acc1.y);
        acc0.z = fmaf(w0, hv.z, acc0.z); acc1.z = fmaf(w1, hv.z, acc1.z);
        acc0.w = fmaf(w0, hv.w, acc0.w); acc1.w = fmaf(w1, hv.w, acc1.w);
    }

    float4 hv0 = h0r[(size_t)nc * 16 + l];
    float4 hv1 = h1r[(size_t)nc * 16 + l];
    float rd0 = 1.f / den0, rd1 = 1.f / den1;
    float4 o;
    o.x = (acc0.x + selfp0 * hv0.x) * rd0 + (acc1.x + selfp1 * hv1.x) * rd1 + bv.x;
    o.y = (acc0.y + selfp0 * hv0.y) * rd0 + (acc1.y + selfp1 * hv1.y) * rd1 + bv.y;
    o.z = (acc0.z + selfp0 * hv0.z) * rd0 + (acc1.z + selfp1 * hv1.z) * rd1 + bv.z;
    o.w = (acc0.w + selfp0 * hv0.w) * rd0 + (acc1.w + selfp1 * hv1.w) * rd1 + bv.w;

    if (live)
        reinterpret_cast<float4*>(out)[(size_t)node * 16 + l] = o;
}

// ---------------- launch -----------------------------------------------------
extern "C" void kernel_launch(void* const* d_in, const int* in_sizes, int n_in,
                              void* d_out, int out_size)
{
    const float* x   = (const float*)d_in[0];
    const int*   ei  = (const int*)  d_in[1];
    const int*   et  = (const int*)  d_in[2];
    const float* W0  = (const float*)d_in[3];
    const float* as0 = (const float*)d_in[4];
    const float* ad0 = (const float*)d_in[5];
    const float* b0  = (const float*)d_in[6];
    const float* W1  = (const float*)d_in[7];
    const float* as1 = (const float*)d_in[8];
    const float* ad1 = (const float*)d_in[9];
    const float* b1  = (const float*)d_in[10];
    float* out = (float*)d_out;

    int N = in_sizes[0] / DIM;
    int E = in_sizes[1] / 2;
    if (N > MAXN) N = MAXN;
    if (E > MAXE) E = MAXE;

    const int* srcp = ei;
    const int* dstp = ei + E;

    // One resident wave: 148 SMs x 3 blocks/SM (74 regs) = 444 blocks.
    int nChunks = (N + 7) / 8;
    int gemmBlocks = (nChunks + 7) / 8;
    if (gemmBlocks > 444) gemmBlocks = 444;

    k_gemm  <<<gemmBlocks, 256>>>(x, W0, W1, as0, ad0, as1, ad1, N);
    k_place <<<(E / 4 + 255) / 256 + 1, 256>>>(srcp, dstp, et, E);
    k_gather<<<(N + 15) / 16, 256>>>(b0, b1, out, N);
}

// round 17
// speedup vs baseline: 1.1826x; 1.0916x over previous
#include <cuda_runtime.h>
#include <cuda_bf16.h>
#include <cstdint>

// Problem dims (fixed by the dataset): N=100000, E=1000000, in=out=64
#define MAXN 100000
#define MAXE 1000000
#define DIM 64
#define BUCKET 64          // per-node edge bucket capacity (deg ~ Poisson(10))

// ---------------- scratch (static device globals; no allocation) -----------
__device__ float g_h0[MAXN * DIM];   // h for branch 0 (login)
__device__ float g_h1[MAXN * DIM];   // h for branch 1 (exec)
__device__ float g_s0[MAXN], g_d0[MAXN], g_s1[MAXN], g_d1[MAXN];

__device__ int    g_cnt[MAXN];              // per-dst in-degree / insert cursor
__device__ float2 g_bucket[MAXN * BUCKET];  // {bits(src|type<<30), p}, 51.2 MB

__device__ __forceinline__ float leakyf(float v) {
    return v > 0.f ? v : 0.2f * v;
}

// Packed f32x2 FMA (Blackwell-only; 2x fp32 FMA throughput)
#define FMA_F32X2(d, a, b, c) \
    asm("fma.rn.f32x2 %0, %1, %2, %3;" \
        : "=l"(d) : "l"(a), "l"(b), "l"(c))
#define PACK2(out, lo, hi) \
    asm("mov.b64 %0, {%1, %2};" : "=l"(out) : "r"(lo), "r"(hi))
#define UNPACK2(lo, hi, in) \
    asm("mov.b64 {%0, %1}, %2;" : "=r"(lo), "=r"(hi) : "l"(in))

#define XS_STRIDE 12   // floats per k-row (8 nodes + 4 pad; 48B -> 16B aligned)

// ---------------- K1: h = x@W via fma.rn.f32x2; s/d scalars; cnt=0 ----------
// x-pair loads via two broadcast LDS.128 (ulonglong2) instead of 4 LDS.64:
// LDS wavefronts per k drop 8 -> 6.
__global__ __launch_bounds__(256) void k_gemm(
    const float* __restrict__ x,
    const float* __restrict__ W0, const float* __restrict__ W1,
    const float* __restrict__ as0, const float* __restrict__ ad0,
    const float* __restrict__ as1, const float* __restrict__ ad1,
    int N)
{
    __shared__ float Ws[2 * DIM * DIM];                       // 32 KB
    __shared__ __align__(16) float xs[8][DIM * XS_STRIDE];    // 24 KB

    int tid = threadIdx.x;
    for (int i = tid; i < DIM * DIM; i += 256) {
        Ws[i] = W0[i];
        Ws[DIM * DIM + i] = W1[i];
    }
    __syncthreads();

    int warp = tid >> 5, lane = tid & 31;
    int sel = lane >> 4;          // 0 -> branch0, 1 -> branch1
    int li  = lane & 15;          // 16 lanes cover 64 cols (4 each)
    const float* myW = Ws + sel * DIM * DIM;
    float4 asv = *reinterpret_cast<const float4*>((sel ? as1 : as0) + 4 * li);
    float4 adv = *reinterpret_cast<const float4*>((sel ? ad1 : ad0) + 4 * li);
    float* myH = sel ? g_h1 : g_h0;
    float* myS = sel ? g_s1 : g_s0;
    float* myD = sel ? g_d1 : g_d0;

    int nChunks = (N + 7) >> 3;
    for (int chunk = blockIdx.x * 8 + warp; chunk < nChunks; chunk += gridDim.x * 8) {
        int base = chunk * 8;
        int count = min(8, N - base);

        // stage x transposed: xs[k*XS_STRIDE + r] = x[base+r][k]
        {
            const float4* x4 = reinterpret_cast<const float4*>(x) + (size_t)base * 16;
            float* xw = xs[warp];
            for (int i = lane; i < 128; i += 32) {
                int r = i >> 4, k4 = i & 15;
                float4 v = (r < count) ? x4[i] : make_float4(0.f, 0.f, 0.f, 0.f);
                xw[(4 * k4 + 0) * XS_STRIDE + r] = v.x;
                xw[(4 * k4 + 1) * XS_STRIDE + r] = v.y;
                xw[(4 * k4 + 2) * XS_STRIDE + r] = v.z;
                xw[(4 * k4 + 3) * XS_STRIDE + r] = v.w;
            }
        }
        __syncwarp();

        unsigned long long accp[4][4];
#pragma unroll
        for (int p = 0; p < 4; p++)
#pragma unroll
            for (int c = 0; c < 4; c++) accp[p][c] = 0ull;

        const float* xw = xs[warp];
#pragma unroll 8
        for (int k = 0; k < DIM; k++) {
            float4 wv = *reinterpret_cast<const float4*>(myW + k * DIM + 4 * li);
            unsigned long long b[4];
            PACK2(b[0], __float_as_uint(wv.x), __float_as_uint(wv.x));
            PACK2(b[1], __float_as_uint(wv.y), __float_as_uint(wv.y));
            PACK2(b[2], __float_as_uint(wv.z), __float_as_uint(wv.z));
            PACK2(b[3], __float_as_uint(wv.w), __float_as_uint(wv.w));
            const float* xrow = xw + k * XS_STRIDE;
            ulonglong2 va = *reinterpret_cast<const ulonglong2*>(xrow);      // nodes 0-3
            ulonglong2 vb = *reinterpret_cast<const ulonglong2*>(xrow + 4);  // nodes 4-7
            unsigned long long a0 = va.x, a1 = va.y, a2 = vb.x, a3 = vb.y;
#pragma unroll
            for (int c = 0; c < 4; c++) {
                FMA_F32X2(accp[0][c], a0, b[c], accp[0][c]);
                FMA_F32X2(accp[1][c], a1, b[c], accp[1][c]);
                FMA_F32X2(accp[2][c], a2, b[c], accp[2][c]);
                FMA_F32X2(accp[3][c], a3, b[c], accp[3][c]);
            }
        }

        float hval[8][4];
#pragma unroll
        for (int p = 0; p < 4; p++)
#pragma unroll
            for (int c = 0; c < 4; c++) {
                unsigned lo, hi;
                UNPACK2(lo, hi, accp[p][c]);
                hval[2 * p][c] = __uint_as_float(lo);
                hval[2 * p + 1][c] = __uint_as_float(hi);
            }

        for (int r = 0; r < count; r++) {
            int node = base + r;
            float4 hv = make_float4(hval[r][0], hval[r][1], hval[r][2], hval[r][3]);
            *reinterpret_cast<float4*>(myH + (size_t)node * DIM + 4 * li) = hv;

            float ps = hv.x * asv.x + hv.y * asv.y + hv.z * asv.z + hv.w * asv.w;
            float pd = hv.x * adv.x + hv.y * adv.y + hv.z * adv.z + hv.w * adv.w;
#pragma unroll
            for (int off = 8; off > 0; off >>= 1) {
                ps += __shfl_down_sync(0xffffffffu, ps, off, 16);
                pd += __shfl_down_sync(0xffffffffu, pd, off, 16);
            }
            if (li == 0) {
                myS[node] = ps;
                myD[node] = pd;
                if (sel == 0) g_cnt[node] = 0;   // bucket cursor reset
            }
        }
        __syncwarp();
    }
}

// ---------------- K2: edge pass — p + bucket placement -----------------------
__global__ __launch_bounds__(256) void k_place(
    const int* __restrict__ src, const int* __restrict__ dst,
    const int* __restrict__ etype, int E)
{
    int e4 = blockIdx.x * 256 + threadIdx.x;
    int base = e4 * 4;
    if (base >= E) return;

    int nE = min(4, E - base);
    int ss[4], dd[4], tt[4];
    if (nE == 4) {
        int4 sv = reinterpret_cast<const int4*>(src)[e4];
        int4 dv = reinterpret_cast<const int4*>(dst)[e4];
        int4 tv = reinterpret_cast<const int4*>(etype)[e4];
        ss[0] = sv.x; ss[1] = sv.y; ss[2] = sv.z; ss[3] = sv.w;
        dd[0] = dv.x; dd[1] = dv.y; dd[2] = dv.z; dd[3] = dv.w;
        tt[0] = tv.x; tt[1] = tv.y; tt[2] = tv.z; tt[3] = tv.w;
    } else {
        for (int i = 0; i < nE; i++) {
            ss[i] = src[base + i]; dd[i] = dst[base + i]; tt[i] = etype[base + i];
        }
    }
#pragma unroll 4
    for (int i = 0; i < 4; i++) {
        if (i >= nE) break;
        int s = ss[i], d = dd[i], t = tt[i];
        float sv = t ? g_s1[s] : g_s0[s];
        float dv = t ? g_d1[d] : g_d0[d];
        float p = __expf(leakyf(sv + dv));
        int pos = atomicAdd(&g_cnt[d], 1);
        if (pos < BUCKET)   // unreachable for Poisson(10) degrees; guards OOB
            g_bucket[(size_t)d * BUCKET + pos] =
                make_float2(__int_as_float(s | (t << 30)), p);
    }
}

// ---------------- K3: gather — out[d] = Σ_t (acc_t + self_t·h_t)/den_t + b --
__global__ __launch_bounds__(256) void k_gather(
    const float* __restrict__ b0, const float* __restrict__ b1,
    float* __restrict__ out, int N)
{
    int gw = (blockIdx.x * blockDim.x + threadIdx.x) >> 5;
    int lane = threadIdx.x & 31;
    int sub = lane >> 4;
    int l = lane & 15;

    float4 bv;
    {
        float4 bb0 = reinterpret_cast<const float4*>(b0)[l];
        float4 bb1 = reinterpret_cast<const float4*>(b1)[l];
        bv = make_float4(bb0.x + bb1.x, bb0.y + bb1.y, bb0.z + bb1.z, bb0.w + bb1.w);
    }

    int node = gw * 2 + sub;
    bool live = node < N;
    int nc = live ? node : (N - 1);

    float selfp0 = __expf(leakyf(g_s0[nc] + g_d0[nc]));
    float selfp1 = __expf(leakyf(g_s1[nc] + g_d1[nc]));
    float den0 = selfp0, den1 = selfp1;

    const float4* h0r = reinterpret_cast<const float4*>(g_h0);
    const float4* h1r = reinterpret_cast<const float4*>(g_h1);

    float4 acc0 = make_float4(0.f, 0.f, 0.f, 0.f);
    float4 acc1 = make_float4(0.f, 0.f, 0.f, 0.f);

    int cnt = min(g_cnt[nc], BUCKET);
    const float2* bucket = g_bucket + (size_t)nc * BUCKET;
    for (int ei = 0; ei < cnt; ei++) {
        float2 ev = bucket[ei];                 // uniform address -> broadcast
        int pk = __float_as_int(ev.x);
        int s = pk & 0x3FFFFFFF;
        float ft = (float)(((unsigned)pk) >> 30);
        float w1 = ev.y * ft;
        float w0 = ev.y - w1;
        den0 += w0; den1 += w1;
        const float4* hp = (ft != 0.f ? h1r : h0r) + (size_t)s * 16;
        float4 hv = hp[l];
        acc0.x = fmaf(w0, hv.x, acc0.x); acc1.x = fmaf(w1, hv.x, acc1.x);
        acc0.y = fmaf(w0, hv.y, acc0.y); acc1.y = fmaf(w1, hv.y, acc1.y);
        acc0.z = fmaf(w0, hv.z, acc0.z); acc1.z = fmaf(w1, hv.z, acc1.z);
        acc0.w = fmaf(w0, hv.w, acc0.w); acc1.w = fmaf(w1, hv.w, acc1.w);
    }

    float4 hv0 = h0r[(size_t)nc * 16 + l];
    float4 hv1 = h1r[(size_t)nc * 16 + l];
    float rd0 = 1.f / den0, rd1 = 1.f / den1;
    float4 o;
    o.x = (acc0.x + selfp0 * hv0.x) * rd0 + (acc1.x + selfp1 * hv1.x) * rd1 + bv.x;
    o.y = (acc0.y + selfp0 * hv0.y) * rd0 + (acc1.y + selfp1 * hv1.y) * rd1 + bv.y;
    o.z = (acc0.z + selfp0 * hv0.z) * rd0 + (acc1.z + selfp1 * hv1.z) * rd1 + bv.z;
    o.w = (acc0.w + selfp0 * hv0.w) * rd0 + (acc1.w + selfp1 * hv1.w) * rd1 + bv.w;

    if (live)
        reinterpret_cast<float4*>(out)[(size_t)node * 16 + l] = o;
}

// ---------------- launch -----------------------------------------------------
extern "C" void kernel_launch(void* const* d_in, const int* in_sizes, int n_in,
                              void* d_out, int out_size)
{
    const float* x   = (const float*)d_in[0];
    const int*   ei  = (const int*)  d_in[1];
    const int*   et  = (const int*)  d_in[2];
    const float* W0  = (const float*)d_in[3];
    const float* as0 = (const float*)d_in[4];
    const float* ad0 = (const float*)d_in[5];
    const float* b0  = (const float*)d_in[6];
    const float* W1  = (const float*)d_in[7];
    const float* as1 = (const float*)d_in[8];
    const float* ad1 = (const float*)d_in[9];
    const float* b1  = (const float*)d_in[10];
    float* out = (float*)d_out;

    int N = in_sizes[0] / DIM;
    int E = in_sizes[1] / 2;
    if (N > MAXN) N = MAXN;
    if (E > MAXE) E = MAXE;

    const int* srcp = ei;
    const int* dstp = ei + E;

    // One resident wave: 148 SMs x 3 blocks/SM (74 regs, 56KB smem) = 444.
    int nChunks = (N + 7) / 8;
    int gemmBlocks = (nChunks + 7) / 8;
    if (gemmBlocks > 444) gemmBlocks = 444;

    k_gemm  <<<gemmBlocks, 256>>>(x, W0, W1, as0, ad0, as1, ad1, N);
    k_place <<<(E / 4 + 255) / 256 + 1, 256>>>(srcp, dstp, et, E);
    k_gather<<<(N + 15) / 16, 256>>>(b0, b1, out, N);
}